// round 6
// baseline (speedup 1.0000x reference)
#include <cuda_runtime.h>
#include <math.h>

#define C        144
#define W        77
#define KW       10
#define FC       64
#define CONV_OUT 68                    // W - KW + 1
#define CONCAT   (C*FC + CONV_OUT)     // 9284
#define H2       128
#define GRID     C                     // one block per channel, 1 per SM
#define NT       1024                  // 32 warps per block

// Scratch (no device allocation allowed); zeroed at load, reset by last block.
__device__ __align__(16) float g_h[H2];
__device__ unsigned int g_cnt = 0u;

__device__ __forceinline__ float warp_reduce(float v) {
#pragma unroll
    for (int o = 16; o > 0; o >>= 1) v += __shfl_down_sync(0xffffffffu, v, o);
    return v;
}

__device__ __forceinline__ float dot4(float4 a, float4 b) {
    return a.x * b.x + a.y * b.y + a.z * b.z + a.w * b.w;
}

// ---------------------------------------------------------------------------
// Barrier-free fused kernel, one 1024-thread block per channel.
//   Block c computes BOTH its FC columns' and its conv contribution to h:
//     g_h[j] += w2[j, c*64:(c+1)*64] . fc_vals_c
//             + w2[j, 9216:9284]     . corr_c          (linearity of conv sum)
//   corr_c[t] = sum_k x[c, t+k] * conv_w[c, k]; block 0 also folds conv_b.
//   One RED per (row, block). Last block (counter) does the ~400-flop tail:
//   out = sigmoid(relu(w3 . relu(g_h + b2) + b3)), then resets scratch.
// ---------------------------------------------------------------------------
__global__ __launch_bounds__(NT, 1) void fused_kernel(
    const float* __restrict__ x,       // [C, W]
    const float* __restrict__ fc_w,    // [C, FC, W]
    const float* __restrict__ fc_b,    // [C, FC]
    const float* __restrict__ conv_w,  // [C, KW]
    const float* __restrict__ conv_b,  // [1]
    const float* __restrict__ w2,      // [H2, CONCAT]
    const float* __restrict__ b2,      // [H2]
    const float* __restrict__ w3,      // [1, H2]
    const float* __restrict__ b3,      // [1]
    float* __restrict__ out)           // [1]
{
    const int tid  = threadIdx.x;
    const int lane = tid & 31;
    const int warp = tid >> 5;
    const int c    = blockIdx.x;

    const int j = tid >> 3;            // 0..127 : w2 row owned by this thread
    const int p = tid & 7;             // 0..7   : position within row group

    __shared__ float xs[W];
    __shared__ float cw[KW];
    __shared__ __align__(16) float vals[FC];
    __shared__ __align__(16) float convv[CONV_OUT];
    __shared__ float sm_h[H2];
    __shared__ unsigned int s_last;

    // ---- stage 0: x row + conv weights into smem ----
    if (tid < W)               xs[tid]     = x[c * W + tid];
    else if (tid < W + KW)     cw[tid - W] = conv_w[c * KW + (tid - W)];

    // ---- stage 1: front-batch ALL w2 loads for this thread (max MLP) ----
    // FC slice: row j cols [c*64, c*64+64) = 16 float4; 8 threads/row, 2 each.
    const float4* wrow = reinterpret_cast<const float4*>(
        w2 + (size_t)j * CONCAT + c * FC);
    const float4 a0 = wrow[p];
    const float4 a1 = wrow[p + 8];
    // conv slice: row j cols [9216, 9284) = 17 float4; 2 each + tail at p==0.
    const float4* crow = reinterpret_cast<const float4*>(
        w2 + (size_t)j * CONCAT + C * FC);
    const float4 k0 = crow[p];
    const float4 k1 = crow[p + 8];
    float4 k2 = make_float4(0.f, 0.f, 0.f, 0.f);
    if (p == 0) k2 = crow[16];

    __syncthreads();

    // ---- stage 2: corr_c into smem (no atomics); block 0 folds conv_b ----
    if (tid < CONV_OUT) {
        float s = (c == 0) ? conv_b[0] : 0.f;
#pragma unroll
        for (int k = 0; k < KW; k++) s += xs[tid + k] * cw[k];
        convv[tid] = s;
    }

    // ---- stage 3: FC -- 32 warps x 2 outputs, warp-reduced dots ----
#pragma unroll
    for (int i = 0; i < 2; i++) {
        const int d = warp * 2 + i;                      // 0..63
        const float* row = fc_w + (size_t)(c * FC + d) * W;
        float s = row[lane] * xs[lane] + row[lane + 32] * xs[lane + 32];
        if (lane < W - 64)                               // 13 tail elements
            s += row[lane + 64] * xs[lane + 64];
        s = warp_reduce(s);
        if (lane == 0) vals[d] = s + fc_b[c * FC + d];
    }
    __syncthreads();

    // ---- stage 4: g_h[j] += w2_fc[j,:].vals + w2_conv[j,:].corr ----
    {
        const float4* v4 = reinterpret_cast<const float4*>(vals);
        const float4* c4 = reinterpret_cast<const float4*>(convv);
        float s = dot4(a0, v4[p]) + dot4(a1, v4[p + 8])
                + dot4(k0, c4[p]) + dot4(k1, c4[p + 8]);
        if (p == 0) s += dot4(k2, c4[16]);
#pragma unroll
        for (int o = 4; o > 0; o >>= 1)
            s += __shfl_down_sync(0xffffffffu, s, o, 8);
        if (p == 0) {
            atomicAdd(&g_h[j], s);
            __threadfence();         // release: my RED before my barrier arrive
        }
    }

    // ---- last-block election (no spinning; non-last blocks exit) ----
    __syncthreads();
    if (tid == 0)
        s_last = (atomicAdd(&g_cnt, 1u) == GRID - 1) ? 1u : 0u;
    __syncthreads();
    if (s_last == 0u) return;

    // =================== finalization (last block only) ===================
    __threadfence();                 // acquire: see all blocks' g_h REDs

    if (tid < H2) {
        const float pre = g_h[tid] + b2[tid];
        sm_h[tid] = fmaxf(pre, 0.f) * w3[tid];
        g_h[tid]  = 0.f;             // reset for next replay
    }
    __syncthreads();

    if (warp == 0) {
        float v = sm_h[lane] + sm_h[lane + 32]
                + sm_h[lane + 64] + sm_h[lane + 96];
        v = warp_reduce(v);
        if (lane == 0) {
            const float o2 = fmaxf(v + b3[0], 0.f);
            out[0] = 1.f / (1.f + __expf(-o2));
            g_cnt  = 0u;             // reset for next replay
        }
    }
}

// ---------------------------------------------------------------------------
extern "C" void kernel_launch(void* const* d_in, const int* in_sizes, int n_in,
                              void* d_out, int out_size) {
    const float* x      = (const float*)d_in[0];
    const float* fc_w   = (const float*)d_in[1];
    const float* fc_b   = (const float*)d_in[2];
    const float* conv_w = (const float*)d_in[3];
    const float* conv_b = (const float*)d_in[4];
    const float* w2     = (const float*)d_in[5];
    const float* b2     = (const float*)d_in[6];
    const float* w3     = (const float*)d_in[7];
    const float* b3     = (const float*)d_in[8];

    fused_kernel<<<GRID, NT>>>(x, fc_w, fc_b, conv_w, conv_b,
                               w2, b2, w3, b3, (float*)d_out);
}